// round 1
// baseline (speedup 1.0000x reference)
#include <cuda_runtime.h>

// Problem constants
#define Nn 50000
#define Hh 512
#define Dd 256
#define Ee 200000
#define Pp 100000
#define Rr 3
#define KS 2048   // 4*H stacked K dimension

// ---------------- scratch (device globals; no allocation) ----------------
__device__ float g_x [(size_t)Nn * Hh];   // current node features [N,512]
__device__ float g_xs[(size_t)Nn * KS];   // stacked [x | agg0 | agg1 | agg2]
__device__ float g_h [(size_t)Nn * Hh];   // layer-2 pre-LN output
__device__ float g_z [(size_t)Nn * Dd];   // final node embeddings [N,256]
__device__ float g_h1[(size_t)Pp * Dd];   // pair hidden (post-BN) [P,256]

// ---------------- encode: x = node_emb + type_emb[type] ----------------
__global__ void encode_k(const int* __restrict__ types,
                         const float* __restrict__ node_emb,
                         const float* __restrict__ type_emb) {
    int i = blockIdx.x * blockDim.x + threadIdx.x;     // over N*H/4
    if (i >= Nn * (Hh / 4)) return;
    int n = i / (Hh / 4);
    int q = i % (Hh / 4);
    float4 a = ((const float4*)node_emb)[i];
    float4 b = ((const float4*)type_emb)[(size_t)types[n] * (Hh / 4) + q];
    a.x += b.x; a.y += b.y; a.z += b.z; a.w += b.w;
    ((float4*)g_x)[i] = a;
}

// ---------------- XS build: first H cols = x, rest zero ----------------
__global__ void build_xs_k() {
    long i = (long)blockIdx.x * blockDim.x + threadIdx.x;  // over N*KS/4
    if (i >= (long)Nn * (KS / 4)) return;
    int n = (int)(i / (KS / 4));
    int q = (int)(i % (KS / 4));
    float4 v = make_float4(0.f, 0.f, 0.f, 0.f);
    if (q < Hh / 4) v = ((const float4*)g_x)[(size_t)n * (Hh / 4) + q];
    ((float4*)g_xs)[i] = v;
}

// ---------------- edge scatter: xs[dst, roff + :] += x[src, :] ----------------
__global__ void scatter_k(const int* __restrict__ src,
                          const int* __restrict__ dst, int roff) {
    long t = (long)blockIdx.x * blockDim.x + threadIdx.x;  // E * (H/4)
    if (t >= (long)Ee * (Hh / 4)) return;
    int e = (int)(t / (Hh / 4));
    int q = (int)(t % (Hh / 4));
    int s = src[e], d = dst[e];
    float4 v = ((const float4*)(g_x + (size_t)s * Hh))[q];
    float* p = g_xs + (size_t)d * KS + roff + q * 4;
    atomicAdd(p + 0, v.x);
    atomicAdd(p + 1, v.y);
    atomicAdd(p + 2, v.z);
    atomicAdd(p + 3, v.w);
}

// ---------------- SGEMM: out[N,HO] = g_xs[N,2048] @ Wstack[2048,HO] ----------------
// Wstack row k:  k < 512 -> wl + k*HO ; else wr + (k-512)*HO   (w_rel is [R,H,HO] contiguous)
// OUTSEL: 0 -> g_x (with relu), 1 -> g_h, 2 -> g_z
template <int HO, bool RELU, int OUTSEL>
__global__ void rgcn_gemm_k(const float* __restrict__ wl,
                            const float* __restrict__ wr) {
    __shared__ __align__(16) float As[16][64];
    __shared__ __align__(16) float Bs[16][64];

    const int tid = threadIdx.x;            // 256 threads
    const int tx = tid % 16, ty = tid / 16; // compute 4x4 tile at (ty*4, tx*4)
    const int a_r = tid / 4, a_c = tid % 4; // A load: row, col-group
    const int b_r = tid / 16, b_c = tid % 16;

    const int m0 = blockIdx.y * 64;
    const int n0 = blockIdx.x * 64;

    float acc[4][4];
#pragma unroll
    for (int i = 0; i < 4; i++)
#pragma unroll
        for (int j = 0; j < 4; j++) acc[i][j] = 0.f;

    for (int k0 = 0; k0 < KS; k0 += 16) {
        // load A tile 64x16
        int gm = m0 + a_r;
        float4 av = make_float4(0.f, 0.f, 0.f, 0.f);
        if (gm < Nn)
            av = *(const float4*)(g_xs + (size_t)gm * KS + k0 + a_c * 4);
        As[a_c * 4 + 0][a_r] = av.x;
        As[a_c * 4 + 1][a_r] = av.y;
        As[a_c * 4 + 2][a_r] = av.z;
        As[a_c * 4 + 3][a_r] = av.w;
        // load B tile 16x64
        int k = k0 + b_r;
        const float* brow = (k < Hh) ? (wl + (size_t)k * HO)
                                     : (wr + (size_t)(k - Hh) * HO);
        *(float4*)&Bs[b_r][b_c * 4] = *(const float4*)(brow + n0 + b_c * 4);
        __syncthreads();
#pragma unroll
        for (int kk = 0; kk < 16; kk++) {
            float4 a = *(const float4*)&As[kk][ty * 4];
            float4 b = *(const float4*)&Bs[kk][tx * 4];
            float aa[4] = {a.x, a.y, a.z, a.w};
            float bb[4] = {b.x, b.y, b.z, b.w};
#pragma unroll
            for (int i = 0; i < 4; i++)
#pragma unroll
                for (int j = 0; j < 4; j++) acc[i][j] += aa[i] * bb[j];
        }
        __syncthreads();
    }

    float* out = (OUTSEL == 0) ? g_x : (OUTSEL == 1) ? g_h : g_z;
#pragma unroll
    for (int i = 0; i < 4; i++) {
        int gm = m0 + ty * 4 + i;
        if (gm >= Nn) continue;
#pragma unroll
        for (int j = 0; j < 4; j++) {
            float v = acc[i][j];
            if (RELU) v = fmaxf(v, 0.f);
            out[(size_t)gm * HO + n0 + tx * 4 + j] = v;
        }
    }
}

// ---------------- fused LayerNorm + ReLU + residual add into g_x ----------------
__global__ void ln_relu_add_k(const float* __restrict__ lng,
                              const float* __restrict__ lnb) {
    int n = blockIdx.x;
    int t = threadIdx.x;  // 128 threads, 4 elems each via float4
    const float4 v = ((const float4*)(g_h + (size_t)n * Hh))[t];
    float s = v.x + v.y + v.z + v.w;
    float ss = v.x * v.x + v.y * v.y + v.z * v.z + v.w * v.w;
#pragma unroll
    for (int o = 16; o; o >>= 1) {
        s += __shfl_xor_sync(0xffffffff, s, o);
        ss += __shfl_xor_sync(0xffffffff, ss, o);
    }
    __shared__ float sm[4], sm2[4];
    if ((t & 31) == 0) { sm[t >> 5] = s; sm2[t >> 5] = ss; }
    __syncthreads();
    s = sm[0] + sm[1] + sm[2] + sm[3];
    ss = sm2[0] + sm2[1] + sm2[2] + sm2[3];
    float mu = s * (1.f / Hh);
    float var = ss * (1.f / Hh) - mu * mu;
    float rstd = rsqrtf(var + 1e-5f);
    float4 g = ((const float4*)lng)[t];
    float4 b = ((const float4*)lnb)[t];
    float4* xp = (float4*)(g_x + (size_t)n * Hh) + t;
    float4 xv = *xp;
    xv.x += fmaxf((v.x - mu) * rstd * g.x + b.x, 0.f);
    xv.y += fmaxf((v.y - mu) * rstd * g.y + b.y, 0.f);
    xv.z += fmaxf((v.z - mu) * rstd * g.z + b.z, 0.f);
    xv.w += fmaxf((v.w - mu) * rstd * g.w + b.w, 0.f);
    *xp = xv;
}

// ---------------- pair scoring GEMM: h1 = BN(relu(feats @ W1 + b1)) ----------------
// feats[p,k]: k<256 -> z[sp,k] ; k<512 -> z[dp,k-256] ; else z[sp,k-512]*z[dp,k-512]
__global__ void score_gemm_k(const float* __restrict__ w1,
                             const float* __restrict__ b1,
                             const float* __restrict__ bng,
                             const float* __restrict__ bnb,
                             const float* __restrict__ bnm,
                             const float* __restrict__ bnv,
                             const int* __restrict__ pairs) {
    __shared__ __align__(16) float As[16][64];
    __shared__ __align__(16) float Bs[16][64];
    __shared__ int sp[64], dp[64];

    const int tid = threadIdx.x;
    const int tx = tid % 16, ty = tid / 16;
    const int a_r = tid / 4, a_c = tid % 4;
    const int b_r = tid / 16, b_c = tid % 16;

    const int m0 = blockIdx.y * 64;
    const int n0 = blockIdx.x * 64;

    if (tid < 64) {
        int p = m0 + tid;
        sp[tid] = (p < Pp) ? pairs[p] : 0;
        dp[tid] = (p < Pp) ? pairs[Pp + p] : 0;
    }
    __syncthreads();

    float acc[4][4];
#pragma unroll
    for (int i = 0; i < 4; i++)
#pragma unroll
        for (int j = 0; j < 4; j++) acc[i][j] = 0.f;

    const int spi = sp[a_r], dpi = dp[a_r];

    for (int k0 = 0; k0 < 3 * Dd; k0 += 16) {
        int k = k0 + a_c * 4;
        float4 av;
        if (k < Dd) {
            av = *(const float4*)(g_z + (size_t)spi * Dd + k);
        } else if (k < 2 * Dd) {
            av = *(const float4*)(g_z + (size_t)dpi * Dd + (k - Dd));
        } else {
            float4 s4 = *(const float4*)(g_z + (size_t)spi * Dd + (k - 2 * Dd));
            float4 d4 = *(const float4*)(g_z + (size_t)dpi * Dd + (k - 2 * Dd));
            av = make_float4(s4.x * d4.x, s4.y * d4.y, s4.z * d4.z, s4.w * d4.w);
        }
        As[a_c * 4 + 0][a_r] = av.x;
        As[a_c * 4 + 1][a_r] = av.y;
        As[a_c * 4 + 2][a_r] = av.z;
        As[a_c * 4 + 3][a_r] = av.w;

        *(float4*)&Bs[b_r][b_c * 4] =
            *(const float4*)(w1 + (size_t)(k0 + b_r) * Dd + n0 + b_c * 4);
        __syncthreads();
#pragma unroll
        for (int kk = 0; kk < 16; kk++) {
            float4 a = *(const float4*)&As[kk][ty * 4];
            float4 b = *(const float4*)&Bs[kk][tx * 4];
            float aa[4] = {a.x, a.y, a.z, a.w};
            float bb[4] = {b.x, b.y, b.z, b.w};
#pragma unroll
            for (int i = 0; i < 4; i++)
#pragma unroll
                for (int j = 0; j < 4; j++) acc[i][j] += aa[i] * bb[j];
        }
        __syncthreads();
    }

#pragma unroll
    for (int i = 0; i < 4; i++) {
        int gp = m0 + ty * 4 + i;
        if (gp >= Pp) continue;
#pragma unroll
        for (int j = 0; j < 4; j++) {
            int col = n0 + tx * 4 + j;
            float v = fmaxf(acc[i][j] + b1[col], 0.f);
            v = (v - bnm[col]) * rsqrtf(bnv[col] + 1e-5f) * bng[col] + bnb[col];
            g_h1[(size_t)gp * Dd + col] = v;
        }
    }
}

// ---------------- final: score = h1 . w2 + b2, degree penalties ----------------
__global__ void final_k(const int* __restrict__ pairs,
                        const int* __restrict__ degrees,
                        const float* __restrict__ w2,
                        const float* __restrict__ b2,
                        const float* __restrict__ alpha,
                        const float* __restrict__ beta,
                        float* __restrict__ out) {
    int warp = (blockIdx.x * blockDim.x + threadIdx.x) >> 5;
    int lane = threadIdx.x & 31;
    if (warp >= Pp) return;
    const float* h1 = g_h1 + (size_t)warp * Dd;
    float s = 0.f;
#pragma unroll
    for (int j = lane; j < Dd; j += 32) s += h1[j] * w2[j];
#pragma unroll
    for (int o = 16; o; o >>= 1) s += __shfl_xor_sync(0xffffffff, s, o);
    if (lane == 0) {
        float sc = s + b2[0];
        int spi = pairs[warp], dpi = pairs[Pp + warp];
        float sd = fmaxf((float)degrees[spi], 1.f);
        float dd = fmaxf((float)degrees[dpi], 1.f);
        float ra = fmaxf(alpha[0], 0.f), rb = fmaxf(beta[0], 0.f);
        float base = sc - ra * logf(sd) - rb * logf(dd);
        out[warp] = base / (sqrtf(sd) * sqrtf(dd) + 1e-8f);
    }
}

// ---------------- launch ----------------
extern "C" void kernel_launch(void* const* d_in, const int* in_sizes, int n_in,
                              void* d_out, int out_size) {
    const int*   types     = (const int*)d_in[0];
    const int*   src0      = (const int*)d_in[1];
    const int*   dst0      = (const int*)d_in[2];
    const int*   src1      = (const int*)d_in[3];
    const int*   dst1      = (const int*)d_in[4];
    const int*   src2      = (const int*)d_in[5];
    const int*   dst2      = (const int*)d_in[6];
    const int*   pairs     = (const int*)d_in[7];
    const int*   degrees   = (const int*)d_in[8];
    const float* node_emb  = (const float*)d_in[9];
    const float* type_emb  = (const float*)d_in[10];
    const float* w_loop_in  = (const float*)d_in[11];
    const float* w_rel_in   = (const float*)d_in[12];
    const float* w_loop_res = (const float*)d_in[13];
    const float* w_rel_res  = (const float*)d_in[14];
    const float* ln_g       = (const float*)d_in[15];
    const float* ln_b       = (const float*)d_in[16];
    const float* w_loop_out = (const float*)d_in[17];
    const float* w_rel_out  = (const float*)d_in[18];
    const float* lp_w1      = (const float*)d_in[19];
    const float* lp_b1      = (const float*)d_in[20];
    const float* bn_g       = (const float*)d_in[21];
    const float* bn_b       = (const float*)d_in[22];
    const float* bn_mean    = (const float*)d_in[23];
    const float* bn_var     = (const float*)d_in[24];
    const float* lp_w2      = (const float*)d_in[25];
    const float* lp_b2      = (const float*)d_in[26];
    const float* alpha      = (const float*)d_in[27];
    const float* beta       = (const float*)d_in[28];
    float* out = (float*)d_out;

    const int ENC_BLKS = (Nn * (Hh / 4) + 255) / 256;
    const int XS_BLKS  = (int)(((long)Nn * (KS / 4) + 255) / 256);
    const int SC_BLKS  = (int)(((long)Ee * (Hh / 4) + 255) / 256);
    const dim3 G1(Hh / 64, (Nn + 63) / 64);       // HO=512 gemm
    const dim3 G3(Dd / 64, (Nn + 63) / 64);       // HO=256 gemm
    const dim3 GS(Dd / 64, (Pp + 63) / 64);       // scoring gemm

    // encode
    encode_k<<<ENC_BLKS, 256>>>(types, node_emb, type_emb);

    // ---- layer 1: x = relu(rgcn(x, w_loop_in, w_rel_in)) ----
    build_xs_k<<<XS_BLKS, 256>>>();
    scatter_k<<<SC_BLKS, 256>>>(src0, dst0, 1 * Hh);
    scatter_k<<<SC_BLKS, 256>>>(src1, dst1, 2 * Hh);
    scatter_k<<<SC_BLKS, 256>>>(src2, dst2, 3 * Hh);
    rgcn_gemm_k<512, true, 0><<<G1, 256>>>(w_loop_in, w_rel_in);

    // ---- layer 2: h = rgcn(x,...); x += relu(LN(h)) ----
    build_xs_k<<<XS_BLKS, 256>>>();
    scatter_k<<<SC_BLKS, 256>>>(src0, dst0, 1 * Hh);
    scatter_k<<<SC_BLKS, 256>>>(src1, dst1, 2 * Hh);
    scatter_k<<<SC_BLKS, 256>>>(src2, dst2, 3 * Hh);
    rgcn_gemm_k<512, false, 1><<<G1, 256>>>(w_loop_res, w_rel_res);
    ln_relu_add_k<<<Nn, 128>>>(ln_g, ln_b);

    // ---- layer 3: z = rgcn(x, w_loop_out, w_rel_out) [N,256] ----
    build_xs_k<<<XS_BLKS, 256>>>();
    scatter_k<<<SC_BLKS, 256>>>(src0, dst0, 1 * Hh);
    scatter_k<<<SC_BLKS, 256>>>(src1, dst1, 2 * Hh);
    scatter_k<<<SC_BLKS, 256>>>(src2, dst2, 3 * Hh);
    rgcn_gemm_k<256, false, 2><<<G3, 256>>>(w_loop_out, w_rel_out);

    // ---- scoring ----
    score_gemm_k<<<GS, 256>>>(lp_w1, lp_b1, bn_g, bn_b, bn_mean, bn_var, pairs);
    final_k<<<(Pp * 32 + 255) / 256, 256>>>(pairs, degrees, lp_w2, lp_b2,
                                            alpha, beta, out);
}

// round 3
// speedup vs baseline: 1.8928x; 1.8928x over previous
#include <cuda_runtime.h>
#include <cuda_bf16.h>
#include <cstdint>

// Problem constants
#define Nn 50000
#define Hh 512
#define Dd 256
#define Ee 200000
#define Pp 100000
#define KS 2048   // 4*H stacked K dimension

// mma tile config
#define MT 128
#define NTT 128
#define KC 32
#define CHUNKS (KS / KC)    // 64
#define SCH (768 / KC)      // 24 (scoring K)

// smem layout per stage (bytes): A/B tiles stored [row][40 bf16] (80B rows)
#define A_HI 0
#define A_LO 10240
#define B_HI 20480
#define B_LO 30720
#define STAGE 40960
#define SMEM_MMA (2 * STAGE)

// ---------------- scratch (device globals; no allocation) ----------------
__device__ float g_x [(size_t)Nn * Hh];
__device__ float g_xs[(size_t)Nn * KS];
__device__ float g_h [(size_t)Nn * Hh];
__device__ float g_z [(size_t)Nn * Dd];
__device__ float g_h1[(size_t)Pp * Dd];
__device__ __align__(16) __nv_bfloat16 g_wt_hi[(size_t)Hh * KS];  // [HO][K]
__device__ __align__(16) __nv_bfloat16 g_wt_lo[(size_t)Hh * KS];

// ======================= PTX helpers (base sm_103 safe) =======================
__device__ __forceinline__ uint32_t smem_u32(const void* p) {
    uint32_t a;
    asm("{ .reg .u64 t; cvta.to.shared.u64 t, %1; cvt.u32.u64 %0, t; }" : "=r"(a) : "l"(p));
    return a;
}
#define STS64(addr, val) \
    asm volatile("st.shared.b64 [%0], %1;" :: "r"(addr), "l"(val) : "memory")
#define CP16(dst, src) \
    asm volatile("cp.async.cg.shared.global [%0], [%1], 16;" :: "r"(dst), "l"(src) : "memory")
#define CPCOMMIT() asm volatile("cp.async.commit_group;" ::: "memory")
#define CPWAIT0()  asm volatile("cp.async.wait_group 0;" ::: "memory")
#define LDSM_X4(r0, r1, r2, r3, addr) \
    asm volatile("ldmatrix.sync.aligned.m8n8.x4.shared.b16 {%0,%1,%2,%3},[%4];" \
                 : "=r"(r0), "=r"(r1), "=r"(r2), "=r"(r3) : "r"(addr))
#define MMA16816(d, a, b) \
    asm volatile("mma.sync.aligned.m16n8k16.row.col.f32.bf16.bf16.f32 " \
                 "{%0,%1,%2,%3},{%4,%5,%6,%7},{%8,%9},{%0,%1,%2,%3};" \
                 : "+f"((d)[0]), "+f"((d)[1]), "+f"((d)[2]), "+f"((d)[3]) \
                 : "r"((a)[0]), "r"((a)[1]), "r"((a)[2]), "r"((a)[3]), \
                   "r"((b)[0]), "r"((b)[1]))

// fp32 -> hi/lo bf16 split, store 8B to hi buffer and lo buffer (+10240)
__device__ __forceinline__ void cvt_sts(uint32_t addr_hi, float4 v) {
    __nv_bfloat162 h0 = __floats2bfloat162_rn(v.x, v.y);
    __nv_bfloat162 h1 = __floats2bfloat162_rn(v.z, v.w);
    float lx = v.x - __low2float(h0);
    float ly = v.y - __high2float(h0);
    float lz = v.z - __low2float(h1);
    float lw = v.w - __high2float(h1);
    __nv_bfloat162 l0 = __floats2bfloat162_rn(lx, ly);
    __nv_bfloat162 l1 = __floats2bfloat162_rn(lz, lw);
    uint32_t uh0 = *reinterpret_cast<uint32_t*>(&h0);
    uint32_t uh1 = *reinterpret_cast<uint32_t*>(&h1);
    uint32_t ul0 = *reinterpret_cast<uint32_t*>(&l0);
    uint32_t ul1 = *reinterpret_cast<uint32_t*>(&l1);
    STS64(addr_hi, ((uint64_t)uh1 << 32) | uh0);
    STS64(addr_hi + 10240u, ((uint64_t)ul1 << 32) | ul0);
}

// one K-chunk (32) of hi/lo 3-pass mma for one warp
__device__ __forceinline__ void mma_chunk(uint32_t base, int wm, int wn, int lane,
                                          float acc[4][4][4]) {
#pragma unroll
    for (int ksf = 0; ksf < 2; ksf++) {
        uint32_t a_addr = base + A_HI +
                          (uint32_t)(wm * 64 + (lane & 15)) * 80u +
                          (uint32_t)(ksf * 16 + (lane >> 4) * 8) * 2u;
        uint32_t ah[4][4], al[4][4];
#pragma unroll
        for (int i = 0; i < 4; i++) {
            LDSM_X4(ah[i][0], ah[i][1], ah[i][2], ah[i][3], a_addr + i * 16 * 80);
            LDSM_X4(al[i][0], al[i][1], al[i][2], al[i][3],
                    a_addr + 10240u + i * 16 * 80);
        }
        int g = lane >> 3;
        uint32_t b_n = (uint32_t)(wn * 32 + ((g >> 1) << 3) + (lane & 7));
        uint32_t b_k = (uint32_t)(ksf * 16 + ((g & 1) << 3));
        uint32_t b_addr = base + B_HI + b_n * 80u + b_k * 2u;
        uint32_t bh[4][2], bl[4][2];
#pragma unroll
        for (int jp = 0; jp < 2; jp++) {
            LDSM_X4(bh[2 * jp][0], bh[2 * jp][1], bh[2 * jp + 1][0], bh[2 * jp + 1][1],
                    b_addr + jp * 16 * 80);
            LDSM_X4(bl[2 * jp][0], bl[2 * jp][1], bl[2 * jp + 1][0], bl[2 * jp + 1][1],
                    b_addr + 10240u + jp * 16 * 80);
        }
#pragma unroll
        for (int i = 0; i < 4; i++)
#pragma unroll
            for (int j = 0; j < 4; j++) {
                MMA16816(acc[i][j], ah[i], bh[j]);
                MMA16816(acc[i][j], ah[i], bl[j]);
                MMA16816(acc[i][j], al[i], bh[j]);
            }
    }
}

// ---------------- encode: x = node_emb + type_emb[type] ----------------
__global__ void encode_k(const int* __restrict__ types,
                         const float* __restrict__ node_emb,
                         const float* __restrict__ type_emb) {
    int i = blockIdx.x * blockDim.x + threadIdx.x;
    if (i >= Nn * (Hh / 4)) return;
    int n = i / (Hh / 4);
    int q = i % (Hh / 4);
    float4 a = ((const float4*)node_emb)[i];
    float4 b = ((const float4*)type_emb)[(size_t)types[n] * (Hh / 4) + q];
    a.x += b.x; a.y += b.y; a.z += b.z; a.w += b.w;
    ((float4*)g_x)[i] = a;
}

// ---------------- XS build ----------------
__global__ void build_xs_k() {
    long i = (long)blockIdx.x * blockDim.x + threadIdx.x;
    if (i >= (long)Nn * (KS / 4)) return;
    int n = (int)(i / (KS / 4));
    int q = (int)(i % (KS / 4));
    float4 v = make_float4(0.f, 0.f, 0.f, 0.f);
    if (q < Hh / 4) v = ((const float4*)g_x)[(size_t)n * (Hh / 4) + q];
    ((float4*)g_xs)[i] = v;
}

// ---------------- edge scatter ----------------
__global__ void scatter_k(const int* __restrict__ src,
                          const int* __restrict__ dst, int roff) {
    long t = (long)blockIdx.x * blockDim.x + threadIdx.x;
    if (t >= (long)Ee * (Hh / 4)) return;
    int e = (int)(t / (Hh / 4));
    int q = (int)(t % (Hh / 4));
    int s = src[e], d = dst[e];
    float4 v = ((const float4*)(g_x + (size_t)s * Hh))[q];
    float* p = g_xs + (size_t)d * KS + roff + q * 4;
    atomicAdd(p + 0, v.x);
    atomicAdd(p + 1, v.y);
    atomicAdd(p + 2, v.z);
    atomicAdd(p + 3, v.w);
}

// ---------------- weight transpose + hi/lo split: g_wt[n][k], stride KS ----------------
__global__ void wt_build_k(const float* __restrict__ wl,
                           const float* __restrict__ wr, int HO) {
    long i = (long)blockIdx.x * blockDim.x + threadIdx.x;
    if (i >= (long)HO * KS) return;
    int n = (int)(i % HO);
    int k = (int)(i / HO);
    float v = (k < Hh) ? wl[(size_t)k * HO + n] : wr[(size_t)(k - Hh) * HO + n];
    __nv_bfloat16 h = __float2bfloat16(v);
    __nv_bfloat16 l = __float2bfloat16(v - __bfloat162float(h));
    g_wt_hi[(size_t)n * KS + k] = h;
    g_wt_lo[(size_t)n * KS + k] = l;
}

// scoring weight: w1 [768][256] -> g_wt[n][k] stride 768
__global__ void wt_build_score_k(const float* __restrict__ w1) {
    int i = blockIdx.x * blockDim.x + threadIdx.x;
    if (i >= 256 * 768) return;
    int n = i % 256;
    int k = i / 256;
    float v = w1[(size_t)k * 256 + n];
    __nv_bfloat16 h = __float2bfloat16(v);
    __nv_bfloat16 l = __float2bfloat16(v - __bfloat162float(h));
    g_wt_hi[(size_t)n * 768 + k] = h;
    g_wt_lo[(size_t)n * 768 + k] = l;
}

// ---------------- RGCN GEMM (mma.sync bf16 hi/lo): out[N,HO] = g_xs @ Wstack ----------------
template <int HO, bool RELU, int OUTSEL>
__global__ void __launch_bounds__(256, 1) rgcn_mma_k() {
    extern __shared__ char sm_[];
    const uint32_t sb = smem_u32(sm_);
    const int tid = threadIdx.x;
    const int wid = tid >> 5, lane = tid & 31;
    const int wm = wid & 1, wn = wid >> 1;
    const int m0 = blockIdx.y * MT;
    const int n0 = blockIdx.x * NTT;

    // A loader: row = tid/2, half ac = tid&1 covers 16 floats (4 float4)
    const int ar = tid >> 1;
    const int ac = tid & 1;
    const bool aok = (m0 + ar) < Nn;
    const float4* agp = (const float4*)(g_xs + (size_t)(m0 + ar) * KS) + ac * 4;
    const uint32_t asts = (uint32_t)ar * 80u + (uint32_t)ac * 32u;

    float acc[4][4][4];
#pragma unroll
    for (int i = 0; i < 4; i++)
#pragma unroll
        for (int j = 0; j < 4; j++)
#pragma unroll
            for (int e = 0; e < 4; e++) acc[i][j][e] = 0.f;

    float4 pref[4];
    // prologue: chunk 0
    {
        const float4* gp = agp;  // c=0
#pragma unroll
        for (int j = 0; j < 4; j++)
            pref[j] = aok ? gp[j] : make_float4(0.f, 0.f, 0.f, 0.f);
#pragma unroll
        for (int it = 0; it < 4; it++) {
            int idx = tid + it * 256;        // 0..1023
            int half = idx >> 9;             // 0 = hi, 1 = lo
            int r = idx & 511;
            int n = r >> 2, q = r & 3;
            const __nv_bfloat16* srcb = half ? g_wt_lo : g_wt_hi;
            uint32_t dst = sb + (half ? B_LO : B_HI) + (uint32_t)n * 80u + (uint32_t)q * 16u;
            CP16(dst, srcb + (size_t)(n0 + n) * KS + 0 * KC + q * 8);
        }
        CPCOMMIT();
#pragma unroll
        for (int j = 0; j < 4; j++)
            cvt_sts(sb + A_HI + asts + j * 8u, pref[j]);
        CPWAIT0();
        __syncthreads();
    }

    for (int c = 0; c < CHUNKS; c++) {
        const int cn = c + 1;
        const uint32_t cur = sb + (uint32_t)(c & 1) * STAGE;
        const uint32_t nxt = sb + (uint32_t)(cn & 1) * STAGE;
        if (cn < CHUNKS) {
            const float4* gp = agp + cn * (KC / 4);
#pragma unroll
            for (int j = 0; j < 4; j++)
                pref[j] = aok ? gp[j] : make_float4(0.f, 0.f, 0.f, 0.f);
#pragma unroll
            for (int it = 0; it < 4; it++) {
                int idx = tid + it * 256;
                int half = idx >> 9;
                int r = idx & 511;
                int n = r >> 2, q = r & 3;
                const __nv_bfloat16* srcb = half ? g_wt_lo : g_wt_hi;
                uint32_t dst = nxt + (half ? B_LO : B_HI) + (uint32_t)n * 80u + (uint32_t)q * 16u;
                CP16(dst, srcb + (size_t)(n0 + n) * KS + cn * KC + q * 8);
            }
            CPCOMMIT();
        }
        mma_chunk(cur, wm, wn, lane, acc);
        if (cn < CHUNKS) {
#pragma unroll
            for (int j = 0; j < 4; j++)
                cvt_sts(nxt + A_HI + asts + j * 8u, pref[j]);
            CPWAIT0();
        }
        __syncthreads();
    }

    // epilogue: direct global stores (float2)
    float* out = (OUTSEL == 0) ? g_x : (OUTSEL == 1) ? g_h : g_z;
#pragma unroll
    for (int i = 0; i < 4; i++) {
        int mr = m0 + wm * 64 + i * 16 + (lane >> 2);
#pragma unroll
        for (int j = 0; j < 4; j++) {
            int col = n0 + wn * 32 + j * 8 + (lane & 3) * 2;
            float2 v0 = make_float2(acc[i][j][0], acc[i][j][1]);
            float2 v1 = make_float2(acc[i][j][2], acc[i][j][3]);
            if (RELU) {
                v0.x = fmaxf(v0.x, 0.f); v0.y = fmaxf(v0.y, 0.f);
                v1.x = fmaxf(v1.x, 0.f); v1.y = fmaxf(v1.y, 0.f);
            }
            if (mr < Nn) *(float2*)(out + (size_t)mr * HO + col) = v0;
            if (mr + 8 < Nn) *(float2*)(out + (size_t)(mr + 8) * HO + col) = v1;
        }
    }
}

// ---------------- scoring GEMM (mma.sync bf16 hi/lo, gathered A) ----------------
__global__ void __launch_bounds__(256, 1) score_mma_k(const int* __restrict__ pairs,
                                                      const float* __restrict__ b1,
                                                      const float* __restrict__ bng,
                                                      const float* __restrict__ bnb,
                                                      const float* __restrict__ bnm,
                                                      const float* __restrict__ bnv) {
    extern __shared__ char sm_[];
    const uint32_t sb = smem_u32(sm_);
    const int tid = threadIdx.x;
    const int wid = tid >> 5, lane = tid & 31;
    const int wm = wid & 1, wn = wid >> 1;
    const int m0 = blockIdx.y * MT;
    const int n0 = blockIdx.x * NTT;

    const int ar = tid >> 1;
    const int ac = tid & 1;
    const int p = m0 + ar;
    const bool aok = p < Pp;
    const int spi = aok ? pairs[p] : 0;
    const int dpi = aok ? pairs[Pp + p] : 0;
    const uint32_t asts = (uint32_t)ar * 80u + (uint32_t)ac * 32u;

    float acc[4][4][4];
#pragma unroll
    for (int i = 0; i < 4; i++)
#pragma unroll
        for (int j = 0; j < 4; j++)
#pragma unroll
            for (int e = 0; e < 4; e++) acc[i][j][e] = 0.f;

    float4 pref[4];

    auto loadA = [&](int c) {
        int k0 = c * KC + ac * 16;
        int seg = k0 >> 8;
        int off = k0 & 255;
        const float4* zs = (const float4*)(g_z + (size_t)spi * Dd + off);
        const float4* zd = (const float4*)(g_z + (size_t)dpi * Dd + off);
#pragma unroll
        for (int j = 0; j < 4; j++) {
            if (!aok) { pref[j] = make_float4(0.f, 0.f, 0.f, 0.f); continue; }
            if (seg == 0) pref[j] = zs[j];
            else if (seg == 1) pref[j] = zd[j];
            else {
                float4 a = zs[j], b = zd[j];
                pref[j] = make_float4(a.x * b.x, a.y * b.y, a.z * b.z, a.w * b.w);
            }
        }
    };
    auto loadB = [&](int c, uint32_t stage) {
#pragma unroll
        for (int it = 0; it < 4; it++) {
            int idx = tid + it * 256;
            int half = idx >> 9;
            int r = idx & 511;
            int n = r >> 2, q = r & 3;
            const __nv_bfloat16* srcb = half ? g_wt_lo : g_wt_hi;
            uint32_t dst = stage + (half ? B_LO : B_HI) + (uint32_t)n * 80u + (uint32_t)q * 16u;
            CP16(dst, srcb + (size_t)(n0 + n) * 768 + c * KC + q * 8);
        }
        CPCOMMIT();
    };

    loadA(0);
    loadB(0, sb);
#pragma unroll
    for (int j = 0; j < 4; j++) cvt_sts(sb + A_HI + asts + j * 8u, pref[j]);
    CPWAIT0();
    __syncthreads();

    for (int c = 0; c < SCH; c++) {
        const int cn = c + 1;
        const uint32_t cur = sb + (uint32_t)(c & 1) * STAGE;
        const uint32_t nxt = sb + (uint32_t)(cn & 1) * STAGE;
        if (cn < SCH) { loadA(cn); loadB(cn, nxt); }
        mma_chunk(cur, wm, wn, lane, acc);
        if (cn < SCH) {
#pragma unroll
            for (int j = 0; j < 4; j++)
                cvt_sts(nxt + A_HI + asts + j * 8u, pref[j]);
            CPWAIT0();
        }
        __syncthreads();
    }

    // epilogue: bias + relu + BN -> g_h1
#pragma unroll
    for (int i = 0; i < 4; i++) {
        int mr = m0 + wm * 64 + i * 16 + (lane >> 2);
#pragma unroll
        for (int j = 0; j < 4; j++) {
            int col = n0 + wn * 32 + j * 8 + (lane & 3) * 2;
            float bia0 = b1[col], bia1 = b1[col + 1];
            float s0 = rsqrtf(bnv[col] + 1e-5f) * bng[col];
            float s1 = rsqrtf(bnv[col + 1] + 1e-5f) * bng[col + 1];
            float m0f = bnm[col], m1f = bnm[col + 1];
            float o0 = bnb[col], o1 = bnb[col + 1];
#pragma unroll
            for (int hh = 0; hh < 2; hh++) {
                int row = mr + hh * 8;
                if (row >= Pp) continue;
                float v0 = fmaxf(acc[i][j][hh * 2 + 0] + bia0, 0.f);
                float v1 = fmaxf(acc[i][j][hh * 2 + 1] + bia1, 0.f);
                v0 = (v0 - m0f) * s0 + o0;
                v1 = (v1 - m1f) * s1 + o1;
                *(float2*)(g_h1 + (size_t)row * Dd + col) = make_float2(v0, v1);
            }
        }
    }
}

// ---------------- fused LayerNorm + ReLU + residual ----------------
__global__ void ln_relu_add_k(const float* __restrict__ lng,
                              const float* __restrict__ lnb) {
    int n = blockIdx.x;
    int t = threadIdx.x;
    const float4 v = ((const float4*)(g_h + (size_t)n * Hh))[t];
    float s = v.x + v.y + v.z + v.w;
    float ss = v.x * v.x + v.y * v.y + v.z * v.z + v.w * v.w;
#pragma unroll
    for (int o = 16; o; o >>= 1) {
        s += __shfl_xor_sync(0xffffffff, s, o);
        ss += __shfl_xor_sync(0xffffffff, ss, o);
    }
    __shared__ float sm[4], sm2[4];
    if ((t & 31) == 0) { sm[t >> 5] = s; sm2[t >> 5] = ss; }
    __syncthreads();
    s = sm[0] + sm[1] + sm[2] + sm[3];
    ss = sm2[0] + sm2[1] + sm2[2] + sm2[3];
    float mu = s * (1.f / Hh);
    float var = ss * (1.f / Hh) - mu * mu;
    float rstd = rsqrtf(var + 1e-5f);
    float4 g = ((const float4*)lng)[t];
    float4 b = ((const float4*)lnb)[t];
    float4* xp = (float4*)(g_x + (size_t)n * Hh) + t;
    float4 xv = *xp;
    xv.x += fmaxf((v.x - mu) * rstd * g.x + b.x, 0.f);
    xv.y += fmaxf((v.y - mu) * rstd * g.y + b.y, 0.f);
    xv.z += fmaxf((v.z - mu) * rstd * g.z + b.z, 0.f);
    xv.w += fmaxf((v.w - mu) * rstd * g.w + b.w, 0.f);
    *xp = xv;
}

// ---------------- final reduce ----------------
__global__ void final_k(const int* __restrict__ pairs,
                        const int* __restrict__ degrees,
                        const float* __restrict__ w2,
                        const float* __restrict__ b2,
                        const float* __restrict__ alpha,
                        const float* __restrict__ beta,
                        float* __restrict__ out) {
    int warp = (blockIdx.x * blockDim.x + threadIdx.x) >> 5;
    int lane = threadIdx.x & 31;
    if (warp >= Pp) return;
    const float* h1 = g_h1 + (size_t)warp * Dd;
    float s = 0.f;
#pragma unroll
    for (int j = lane; j < Dd; j += 32) s += h1[j] * w2[j];
#pragma unroll
    for (int o = 16; o; o >>= 1) s += __shfl_xor_sync(0xffffffff, s, o);
    if (lane == 0) {
        float sc = s + b2[0];
        int spi = pairs[warp], dpi = pairs[Pp + warp];
        float sd = fmaxf((float)degrees[spi], 1.f);
        float dd = fmaxf((float)degrees[dpi], 1.f);
        float ra = fmaxf(alpha[0], 0.f), rb = fmaxf(beta[0], 0.f);
        float base = sc - ra * logf(sd) - rb * logf(dd);
        out[warp] = base / (sqrtf(sd) * sqrtf(dd) + 1e-8f);
    }
}

// ---------------- launch ----------------
extern "C" void kernel_launch(void* const* d_in, const int* in_sizes, int n_in,
                              void* d_out, int out_size) {
    const int*   types     = (const int*)d_in[0];
    const int*   src0      = (const int*)d_in[1];
    const int*   dst0      = (const int*)d_in[2];
    const int*   src1      = (const int*)d_in[3];
    const int*   dst1      = (const int*)d_in[4];
    const int*   src2      = (const int*)d_in[5];
    const int*   dst2      = (const int*)d_in[6];
    const int*   pairs     = (const int*)d_in[7];
    const int*   degrees   = (const int*)d_in[8];
    const float* node_emb  = (const float*)d_in[9];
    const float* type_emb  = (const float*)d_in[10];
    const float* w_loop_in  = (const float*)d_in[11];
    const float* w_rel_in   = (const float*)d_in[12];
    const float* w_loop_res = (const float*)d_in[13];
    const float* w_rel_res  = (const float*)d_in[14];
    const float* ln_g       = (const float*)d_in[15];
    const float* ln_b       = (const float*)d_in[16];
    const float* w_loop_out = (const float*)d_in[17];
    const float* w_rel_out  = (const float*)d_in[18];
    const float* lp_w1      = (const float*)d_in[19];
    const float* lp_b1      = (const float*)d_in[20];
    const float* bn_g       = (const float*)d_in[21];
    const float* bn_b       = (const float*)d_in[22];
    const float* bn_mean    = (const float*)d_in[23];
    const float* bn_var     = (const float*)d_in[24];
    const float* lp_w2      = (const float*)d_in[25];
    const float* lp_b2      = (const float*)d_in[26];
    const float* alpha      = (const float*)d_in[27];
    const float* beta       = (const float*)d_in[28];
    float* out = (float*)d_out;

    cudaFuncSetAttribute(rgcn_mma_k<512, true, 0>,
                         cudaFuncAttributeMaxDynamicSharedMemorySize, SMEM_MMA);
    cudaFuncSetAttribute(rgcn_mma_k<512, false, 1>,
                         cudaFuncAttributeMaxDynamicSharedMemorySize, SMEM_MMA);
    cudaFuncSetAttribute(rgcn_mma_k<256, false, 2>,
                         cudaFuncAttributeMaxDynamicSharedMemorySize, SMEM_MMA);
    cudaFuncSetAttribute(score_mma_k,
                         cudaFuncAttributeMaxDynamicSharedMemorySize, SMEM_MMA);

    const int ENC_BLKS = (Nn * (Hh / 4) + 255) / 256;
    const int XS_BLKS  = (int)(((long)Nn * (KS / 4) + 255) / 256);
    const int SC_BLKS  = (int)(((long)Ee * (Hh / 4) + 255) / 256);
    const int WT512    = (int)(((long)512 * KS + 255) / 256);
    const int WT256    = (int)(((long)256 * KS + 255) / 256);
    const int WTS      = (256 * 768 + 255) / 256;
    const dim3 G1(512 / NTT, (Nn + MT - 1) / MT);   // (4, 391)
    const dim3 G3(256 / NTT, (Nn + MT - 1) / MT);   // (2, 391)
    const dim3 GSc(256 / NTT, (Pp + MT - 1) / MT);  // (2, 782)

    encode_k<<<ENC_BLKS, 256>>>(types, node_emb, type_emb);

    // ---- layer 1 ----
    wt_build_k<<<WT512, 256>>>(w_loop_in, w_rel_in, 512);
    build_xs_k<<<XS_BLKS, 256>>>();
    scatter_k<<<SC_BLKS, 256>>>(src0, dst0, 1 * Hh);
    scatter_k<<<SC_BLKS, 256>>>(src1, dst1, 2 * Hh);
    scatter_k<<<SC_BLKS, 256>>>(src2, dst2, 3 * Hh);
    rgcn_mma_k<512, true, 0><<<G1, 256, SMEM_MMA>>>();

    // ---- layer 2 ----
    wt_build_k<<<WT512, 256>>>(w_loop_res, w_rel_res, 512);
    build_xs_k<<<XS_BLKS, 256>>>();
    scatter_k<<<SC_BLKS, 256>>>(src0, dst0, 1 * Hh);
    scatter_k<<<SC_BLKS, 256>>>(src1, dst1, 2 * Hh);
    scatter_k<<<SC_BLKS, 256>>>(src2, dst2, 3 * Hh);
    rgcn_mma_k<512, false, 1><<<G1, 256, SMEM_MMA>>>();
    ln_relu_add_k<<<Nn, 128>>>(ln_g, ln_b);

    // ---- layer 3 ----
    wt_build_k<<<WT256, 256>>>(w_loop_out, w_rel_out, 256);
    build_xs_k<<<XS_BLKS, 256>>>();
    scatter_k<<<SC_BLKS, 256>>>(src0, dst0, 1 * Hh);
    scatter_k<<<SC_BLKS, 256>>>(src1, dst1, 2 * Hh);
    scatter_k<<<SC_BLKS, 256>>>(src2, dst2, 3 * Hh);
    rgcn_mma_k<256, false, 2><<<G3, 256, SMEM_MMA>>>();

    // ---- scoring ----
    wt_build_score_k<<<WTS, 256>>>(lp_w1);
    score_mma_k<<<GSc, 256, SMEM_MMA>>>(pairs, lp_b1, bn_g, bn_b, bn_mean, bn_var);
    final_k<<<(Pp * 32 + 255) / 256, 256>>>(pairs, degrees, lp_w2, lp_b2,
                                            alpha, beta, out);
}

// round 4
// speedup vs baseline: 2.7431x; 1.4492x over previous
#include <cuda_runtime.h>
#include <cuda_bf16.h>
#include <cstdint>

// Problem constants
#define Nn 50000
#define Hh 512
#define Dd 256
#define Ee 200000
#define Pp 100000
#define KS 2048   // 4*H stacked K dimension
#define AGGW 1536 // 3*H agg row width

// mma tile config
#define MT 128
#define NTT 128
#define KC 32
#define CHUNKS (KS / KC)    // 64
#define SCH (768 / KC)      // 24 (scoring K)

// smem layout per stage (bytes): A/B tiles stored [row][40 bf16] (80B rows)
#define A_HI 0
#define A_LO 10240
#define B_HI 20480
#define B_LO 30720
#define STAGE 40960
#define SMEM_MMA (2 * STAGE)

// CSR scan config
#define SCB 256
#define SCNB ((Nn + SCB - 1) / SCB)   // 196

// ---------------- scratch (device globals; no allocation) ----------------
__device__ float g_x [(size_t)Nn * Hh];
__device__ float g_x2[(size_t)Nn * Hh];
__device__ float g_agg[(size_t)Nn * AGGW];
__device__ float g_h [(size_t)Nn * Hh];
__device__ float g_z [(size_t)Nn * Dd];
__device__ float g_h1[(size_t)Pp * Dd];
__device__ __align__(16) __nv_bfloat16 g_wt_hi[(size_t)Hh * KS];  // [HO][K]
__device__ __align__(16) __nv_bfloat16 g_wt_lo[(size_t)Hh * KS];
// CSR
__device__ int g_deg  [3 * Nn];
__device__ int g_start[3 * Nn];
__device__ int g_cur  [3 * Nn];
__device__ int g_part [3 * SCNB];
__device__ int g_csr  [3 * (size_t)Ee];

// ======================= PTX helpers (base sm_103 safe) =======================
__device__ __forceinline__ uint32_t smem_u32(const void* p) {
    uint32_t a;
    asm("{ .reg .u64 t; cvta.to.shared.u64 t, %1; cvt.u32.u64 %0, t; }" : "=r"(a) : "l"(p));
    return a;
}
#define STS64(addr, val) \
    asm volatile("st.shared.b64 [%0], %1;" :: "r"(addr), "l"(val) : "memory")
#define CP16(dst, src) \
    asm volatile("cp.async.cg.shared.global [%0], [%1], 16;" :: "r"(dst), "l"(src) : "memory")
#define CPCOMMIT() asm volatile("cp.async.commit_group;" ::: "memory")
#define CPWAIT0()  asm volatile("cp.async.wait_group 0;" ::: "memory")
#define LDSM_X4(r0, r1, r2, r3, addr) \
    asm volatile("ldmatrix.sync.aligned.m8n8.x4.shared.b16 {%0,%1,%2,%3},[%4];" \
                 : "=r"(r0), "=r"(r1), "=r"(r2), "=r"(r3) : "r"(addr))
#define MMA16816(d, a, b) \
    asm volatile("mma.sync.aligned.m16n8k16.row.col.f32.bf16.bf16.f32 " \
                 "{%0,%1,%2,%3},{%4,%5,%6,%7},{%8,%9},{%0,%1,%2,%3};" \
                 : "+f"((d)[0]), "+f"((d)[1]), "+f"((d)[2]), "+f"((d)[3]) \
                 : "r"((a)[0]), "r"((a)[1]), "r"((a)[2]), "r"((a)[3]), \
                   "r"((b)[0]), "r"((b)[1]))

// fp32 -> hi/lo bf16 split, store 8B to hi buffer and lo buffer (+10240)
__device__ __forceinline__ void cvt_sts(uint32_t addr_hi, float4 v) {
    __nv_bfloat162 h0 = __floats2bfloat162_rn(v.x, v.y);
    __nv_bfloat162 h1 = __floats2bfloat162_rn(v.z, v.w);
    float lx = v.x - __low2float(h0);
    float ly = v.y - __high2float(h0);
    float lz = v.z - __low2float(h1);
    float lw = v.w - __high2float(h1);
    __nv_bfloat162 l0 = __floats2bfloat162_rn(lx, ly);
    __nv_bfloat162 l1 = __floats2bfloat162_rn(lz, lw);
    uint32_t uh0 = *reinterpret_cast<uint32_t*>(&h0);
    uint32_t uh1 = *reinterpret_cast<uint32_t*>(&h1);
    uint32_t ul0 = *reinterpret_cast<uint32_t*>(&l0);
    uint32_t ul1 = *reinterpret_cast<uint32_t*>(&l1);
    STS64(addr_hi, ((uint64_t)uh1 << 32) | uh0);
    STS64(addr_hi + 10240u, ((uint64_t)ul1 << 32) | ul0);
}

// one K-chunk (32) of hi/lo 3-pass mma for one warp
__device__ __forceinline__ void mma_chunk(uint32_t base, int wm, int wn, int lane,
                                          float acc[4][4][4]) {
#pragma unroll
    for (int ksf = 0; ksf < 2; ksf++) {
        uint32_t a_addr = base + A_HI +
                          (uint32_t)(wm * 64 + (lane & 15)) * 80u +
                          (uint32_t)(ksf * 16 + (lane >> 4) * 8) * 2u;
        uint32_t ah[4][4], al[4][4];
#pragma unroll
        for (int i = 0; i < 4; i++) {
            LDSM_X4(ah[i][0], ah[i][1], ah[i][2], ah[i][3], a_addr + i * 16 * 80);
            LDSM_X4(al[i][0], al[i][1], al[i][2], al[i][3],
                    a_addr + 10240u + i * 16 * 80);
        }
        int g = lane >> 3;
        uint32_t b_n = (uint32_t)(wn * 32 + ((g >> 1) << 3) + (lane & 7));
        uint32_t b_k = (uint32_t)(ksf * 16 + ((g & 1) << 3));
        uint32_t b_addr = base + B_HI + b_n * 80u + b_k * 2u;
        uint32_t bh[4][2], bl[4][2];
#pragma unroll
        for (int jp = 0; jp < 2; jp++) {
            LDSM_X4(bh[2 * jp][0], bh[2 * jp][1], bh[2 * jp + 1][0], bh[2 * jp + 1][1],
                    b_addr + jp * 16 * 80);
            LDSM_X4(bl[2 * jp][0], bl[2 * jp][1], bl[2 * jp + 1][0], bl[2 * jp + 1][1],
                    b_addr + 10240u + jp * 16 * 80);
        }
#pragma unroll
        for (int i = 0; i < 4; i++)
#pragma unroll
            for (int j = 0; j < 4; j++) {
                MMA16816(acc[i][j], ah[i], bh[j]);
                MMA16816(acc[i][j], ah[i], bl[j]);
                MMA16816(acc[i][j], al[i], bh[j]);
            }
    }
}

// ---------------- encode ----------------
__global__ void encode_k(const int* __restrict__ types,
                         const float* __restrict__ node_emb,
                         const float* __restrict__ type_emb) {
    int i = blockIdx.x * blockDim.x + threadIdx.x;
    if (i >= Nn * (Hh / 4)) return;
    int n = i / (Hh / 4);
    int q = i % (Hh / 4);
    float4 a = ((const float4*)node_emb)[i];
    float4 b = ((const float4*)type_emb)[(size_t)types[n] * (Hh / 4) + q];
    a.x += b.x; a.y += b.y; a.z += b.z; a.w += b.w;
    ((float4*)g_x)[i] = a;
}

// ---------------- CSR build ----------------
__global__ void csr_zero_k() {
    int i = blockIdx.x * blockDim.x + threadIdx.x;
    if (i < 3 * Nn) { g_deg[i] = 0; g_cur[i] = 0; }
}
__global__ void csr_count_k(const int* __restrict__ d0, const int* __restrict__ d1,
                            const int* __restrict__ d2) {
    int e = blockIdx.x * blockDim.x + threadIdx.x;
    if (e >= Ee) return;
    atomicAdd(&g_deg[0 * Nn + d0[e]], 1);
    atomicAdd(&g_deg[1 * Nn + d1[e]], 1);
    atomicAdd(&g_deg[2 * Nn + d2[e]], 1);
}
__global__ void csr_scan1_k() {   // block partial sums
    __shared__ int sm[SCB];
    int r = blockIdx.y;
    int i = blockIdx.x * SCB + threadIdx.x;
    sm[threadIdx.x] = (i < Nn) ? g_deg[r * Nn + i] : 0;
    __syncthreads();
    for (int o = SCB / 2; o; o >>= 1) {
        if (threadIdx.x < o) sm[threadIdx.x] += sm[threadIdx.x + o];
        __syncthreads();
    }
    if (threadIdx.x == 0) g_part[r * SCNB + blockIdx.x] = sm[0];
}
__global__ void csr_scan2_k() {   // exclusive scan of partials (tiny)
    int r = blockIdx.x;
    if (threadIdx.x) return;
    int s = 0;
    for (int b = 0; b < SCNB; b++) {
        int t = g_part[r * SCNB + b];
        g_part[r * SCNB + b] = s;
        s += t;
    }
}
__global__ void csr_scan3_k() {   // per-chunk exclusive scan + offset
    __shared__ int sm[SCB];
    int r = blockIdx.y;
    int i = blockIdx.x * SCB + threadIdx.x;
    int v = (i < Nn) ? g_deg[r * Nn + i] : 0;
    sm[threadIdx.x] = v;
    __syncthreads();
    for (int o = 1; o < SCB; o <<= 1) {
        int t = (threadIdx.x >= o) ? sm[threadIdx.x - o] : 0;
        __syncthreads();
        sm[threadIdx.x] += t;
        __syncthreads();
    }
    if (i < Nn)
        g_start[r * Nn + i] = g_part[r * SCNB + blockIdx.x] + sm[threadIdx.x] - v;
}
__global__ void csr_fill_k(const int* __restrict__ s0, const int* __restrict__ d0,
                           const int* __restrict__ s1, const int* __restrict__ d1,
                           const int* __restrict__ s2, const int* __restrict__ d2) {
    int e = blockIdx.x * blockDim.x + threadIdx.x;
    if (e >= Ee) return;
    {
        int d = d0[e];
        int p = atomicAdd(&g_cur[0 * Nn + d], 1);
        g_csr[(size_t)0 * Ee + g_start[0 * Nn + d] + p] = s0[e];
    }
    {
        int d = d1[e];
        int p = atomicAdd(&g_cur[1 * Nn + d], 1);
        g_csr[(size_t)1 * Ee + g_start[1 * Nn + d] + p] = s1[e];
    }
    {
        int d = d2[e];
        int p = atomicAdd(&g_cur[2 * Nn + d], 1);
        g_csr[(size_t)2 * Ee + g_start[2 * Nn + d] + p] = s2[e];
    }
}

// ---------------- gather aggregation: g_agg[n][r*512 + :] = sum_e x[src_e] ----------------
__global__ void agg_k(const float* __restrict__ xin) {
    __shared__ int sl[128];
    const int n = blockIdx.x;
    const int r = blockIdx.y;
    const int t = threadIdx.x;   // 128
    const int s = g_start[r * Nn + n];
    const int d = g_deg[r * Nn + n];
    const int* lst = g_csr + (size_t)r * Ee + s;
    float4 acc = make_float4(0.f, 0.f, 0.f, 0.f);
    for (int base = 0; base < d; base += 128) {
        int m = min(128, d - base);
        if (t < m) sl[t] = lst[base + t];
        __syncthreads();
        for (int i = 0; i < m; i++) {
            int src = sl[i];
            float4 v = ((const float4*)(xin + (size_t)src * Hh))[t];
            acc.x += v.x; acc.y += v.y; acc.z += v.z; acc.w += v.w;
        }
        __syncthreads();
    }
    ((float4*)(g_agg + (size_t)n * AGGW + r * Hh))[t] = acc;
}

// ---------------- weight transpose + hi/lo split ----------------
__global__ void wt_build_k(const float* __restrict__ wl,
                           const float* __restrict__ wr, int HO) {
    long i = (long)blockIdx.x * blockDim.x + threadIdx.x;
    if (i >= (long)HO * KS) return;
    int n = (int)(i % HO);
    int k = (int)(i / HO);
    float v = (k < Hh) ? wl[(size_t)k * HO + n] : wr[(size_t)(k - Hh) * HO + n];
    __nv_bfloat16 h = __float2bfloat16(v);
    __nv_bfloat16 l = __float2bfloat16(v - __bfloat162float(h));
    g_wt_hi[(size_t)n * KS + k] = h;
    g_wt_lo[(size_t)n * KS + k] = l;
}
__global__ void wt_build_score_k(const float* __restrict__ w1) {
    int i = blockIdx.x * blockDim.x + threadIdx.x;
    if (i >= 256 * 768) return;
    int n = i % 256;
    int k = i / 256;
    float v = w1[(size_t)k * 256 + n];
    __nv_bfloat16 h = __float2bfloat16(v);
    __nv_bfloat16 l = __float2bfloat16(v - __bfloat162float(h));
    g_wt_hi[(size_t)n * 768 + k] = h;
    g_wt_lo[(size_t)n * 768 + k] = l;
}

// ---------------- RGCN GEMM: out[N,HO] = [xin | g_agg] @ Wstack ----------------
template <int HO, bool RELU>
__global__ void __launch_bounds__(256, 1) rgcn_mma_k(const float* __restrict__ xin,
                                                     float* __restrict__ out) {
    extern __shared__ char sm_[];
    const uint32_t sb = smem_u32(sm_);
    const int tid = threadIdx.x;
    const int wid = tid >> 5, lane = tid & 31;
    const int wm = wid & 1, wn = wid >> 1;
    const int m0 = blockIdx.y * MT;
    const int n0 = blockIdx.x * NTT;

    const int ar = tid >> 1;
    const int ac = tid & 1;
    const bool aok = (m0 + ar) < Nn;
    const int arow = aok ? (m0 + ar) : 0;
    const float4* xrow = (const float4*)(xin + (size_t)arow * Hh);
    const float4* grow = (const float4*)(g_agg + (size_t)arow * AGGW);
    const uint32_t asts = (uint32_t)ar * 80u + (uint32_t)ac * 32u;

    float acc[4][4][4];
#pragma unroll
    for (int i = 0; i < 4; i++)
#pragma unroll
        for (int j = 0; j < 4; j++)
#pragma unroll
            for (int e = 0; e < 4; e++) acc[i][j][e] = 0.f;

    float4 pref[4];
    auto loadA = [&](int c) {
        int f4 = c * 8 + ac * 4;   // float4 index within 2048-wide row
        const float4* p = (f4 < 128) ? (xrow + f4) : (grow + (f4 - 128));
#pragma unroll
        for (int j = 0; j < 4; j++)
            pref[j] = aok ? p[j] : make_float4(0.f, 0.f, 0.f, 0.f);
    };
    auto loadB = [&](int c, uint32_t stage) {
#pragma unroll
        for (int it = 0; it < 4; it++) {
            int idx = tid + it * 256;
            int half = idx >> 9;
            int r = idx & 511;
            int n = r >> 2, q = r & 3;
            const __nv_bfloat16* srcb = half ? g_wt_lo : g_wt_hi;
            uint32_t dst = stage + (half ? B_LO : B_HI) + (uint32_t)n * 80u + (uint32_t)q * 16u;
            CP16(dst, srcb + (size_t)(n0 + n) * KS + c * KC + q * 8);
        }
        CPCOMMIT();
    };

    loadA(0);
    loadB(0, sb);
#pragma unroll
    for (int j = 0; j < 4; j++) cvt_sts(sb + A_HI + asts + j * 8u, pref[j]);
    CPWAIT0();
    __syncthreads();

    for (int c = 0; c < CHUNKS; c++) {
        const int cn = c + 1;
        const uint32_t cur = sb + (uint32_t)(c & 1) * STAGE;
        const uint32_t nxt = sb + (uint32_t)(cn & 1) * STAGE;
        if (cn < CHUNKS) { loadA(cn); loadB(cn, nxt); }
        mma_chunk(cur, wm, wn, lane, acc);
        if (cn < CHUNKS) {
#pragma unroll
            for (int j = 0; j < 4; j++)
                cvt_sts(nxt + A_HI + asts + j * 8u, pref[j]);
            CPWAIT0();
        }
        __syncthreads();
    }

#pragma unroll
    for (int i = 0; i < 4; i++) {
        int mr = m0 + wm * 64 + i * 16 + (lane >> 2);
#pragma unroll
        for (int j = 0; j < 4; j++) {
            int col = n0 + wn * 32 + j * 8 + (lane & 3) * 2;
            float2 v0 = make_float2(acc[i][j][0], acc[i][j][1]);
            float2 v1 = make_float2(acc[i][j][2], acc[i][j][3]);
            if (RELU) {
                v0.x = fmaxf(v0.x, 0.f); v0.y = fmaxf(v0.y, 0.f);
                v1.x = fmaxf(v1.x, 0.f); v1.y = fmaxf(v1.y, 0.f);
            }
            if (mr < Nn) *(float2*)(out + (size_t)mr * HO + col) = v0;
            if (mr + 8 < Nn) *(float2*)(out + (size_t)(mr + 8) * HO + col) = v1;
        }
    }
}

// ---------------- scoring GEMM ----------------
__global__ void __launch_bounds__(256, 1) score_mma_k(const int* __restrict__ pairs,
                                                      const float* __restrict__ b1,
                                                      const float* __restrict__ bng,
                                                      const float* __restrict__ bnb,
                                                      const float* __restrict__ bnm,
                                                      const float* __restrict__ bnv) {
    extern __shared__ char sm_[];
    const uint32_t sb = smem_u32(sm_);
    const int tid = threadIdx.x;
    const int wid = tid >> 5, lane = tid & 31;
    const int wm = wid & 1, wn = wid >> 1;
    const int m0 = blockIdx.y * MT;
    const int n0 = blockIdx.x * NTT;

    const int ar = tid >> 1;
    const int ac = tid & 1;
    const int p = m0 + ar;
    const bool aok = p < Pp;
    const int spi = aok ? pairs[p] : 0;
    const int dpi = aok ? pairs[Pp + p] : 0;
    const uint32_t asts = (uint32_t)ar * 80u + (uint32_t)ac * 32u;

    float acc[4][4][4];
#pragma unroll
    for (int i = 0; i < 4; i++)
#pragma unroll
        for (int j = 0; j < 4; j++)
#pragma unroll
            for (int e = 0; e < 4; e++) acc[i][j][e] = 0.f;

    float4 pref[4];
    auto loadA = [&](int c) {
        int k0 = c * KC + ac * 16;
        int seg = k0 >> 8;
        int off = k0 & 255;
        const float4* zs = (const float4*)(g_z + (size_t)spi * Dd + off);
        const float4* zd = (const float4*)(g_z + (size_t)dpi * Dd + off);
#pragma unroll
        for (int j = 0; j < 4; j++) {
            if (!aok) { pref[j] = make_float4(0.f, 0.f, 0.f, 0.f); continue; }
            if (seg == 0) pref[j] = zs[j];
            else if (seg == 1) pref[j] = zd[j];
            else {
                float4 a = zs[j], b = zd[j];
                pref[j] = make_float4(a.x * b.x, a.y * b.y, a.z * b.z, a.w * b.w);
            }
        }
    };
    auto loadB = [&](int c, uint32_t stage) {
#pragma unroll
        for (int it = 0; it < 4; it++) {
            int idx = tid + it * 256;
            int half = idx >> 9;
            int r = idx & 511;
            int n = r >> 2, q = r & 3;
            const __nv_bfloat16* srcb = half ? g_wt_lo : g_wt_hi;
            uint32_t dst = stage + (half ? B_LO : B_HI) + (uint32_t)n * 80u + (uint32_t)q * 16u;
            CP16(dst, srcb + (size_t)(n0 + n) * 768 + c * KC + q * 8);
        }
        CPCOMMIT();
    };

    loadA(0);
    loadB(0, sb);
#pragma unroll
    for (int j = 0; j < 4; j++) cvt_sts(sb + A_HI + asts + j * 8u, pref[j]);
    CPWAIT0();
    __syncthreads();

    for (int c = 0; c < SCH; c++) {
        const int cn = c + 1;
        const uint32_t cur = sb + (uint32_t)(c & 1) * STAGE;
        const uint32_t nxt = sb + (uint32_t)(cn & 1) * STAGE;
        if (cn < SCH) { loadA(cn); loadB(cn, nxt); }
        mma_chunk(cur, wm, wn, lane, acc);
        if (cn < SCH) {
#pragma unroll
            for (int j = 0; j < 4; j++)
                cvt_sts(nxt + A_HI + asts + j * 8u, pref[j]);
            CPWAIT0();
        }
        __syncthreads();
    }

#pragma unroll
    for (int i = 0; i < 4; i++) {
        int mr = m0 + wm * 64 + i * 16 + (lane >> 2);
#pragma unroll
        for (int j = 0; j < 4; j++) {
            int col = n0 + wn * 32 + j * 8 + (lane & 3) * 2;
            float bia0 = b1[col], bia1 = b1[col + 1];
            float s0 = rsqrtf(bnv[col] + 1e-5f) * bng[col];
            float s1 = rsqrtf(bnv[col + 1] + 1e-5f) * bng[col + 1];
            float m0f = bnm[col], m1f = bnm[col + 1];
            float o0 = bnb[col], o1 = bnb[col + 1];
#pragma unroll
            for (int hh = 0; hh < 2; hh++) {
                int row = mr + hh * 8;
                if (row >= Pp) continue;
                float v0 = fmaxf(acc[i][j][hh * 2 + 0] + bia0, 0.f);
                float v1 = fmaxf(acc[i][j][hh * 2 + 1] + bia1, 0.f);
                v0 = (v0 - m0f) * s0 + o0;
                v1 = (v1 - m1f) * s1 + o1;
                *(float2*)(g_h1 + (size_t)row * Dd + col) = make_float2(v0, v1);
            }
        }
    }
}

// ---------------- fused LayerNorm + ReLU + residual (into g_x2) ----------------
__global__ void ln_relu_add_k(const float* __restrict__ lng,
                              const float* __restrict__ lnb) {
    int n = blockIdx.x;
    int t = threadIdx.x;
    const float4 v = ((const float4*)(g_h + (size_t)n * Hh))[t];
    float s = v.x + v.y + v.z + v.w;
    float ss = v.x * v.x + v.y * v.y + v.z * v.z + v.w * v.w;
#pragma unroll
    for (int o = 16; o; o >>= 1) {
        s += __shfl_xor_sync(0xffffffff, s, o);
        ss += __shfl_xor_sync(0xffffffff, ss, o);
    }
    __shared__ float sm[4], sm2[4];
    if ((t & 31) == 0) { sm[t >> 5] = s; sm2[t >> 5] = ss; }
    __syncthreads();
    s = sm[0] + sm[1] + sm[2] + sm[3];
    ss = sm2[0] + sm2[1] + sm2[2] + sm2[3];
    float mu = s * (1.f / Hh);
    float var = ss * (1.f / Hh) - mu * mu;
    float rstd = rsqrtf(var + 1e-5f);
    float4 g = ((const float4*)lng)[t];
    float4 b = ((const float4*)lnb)[t];
    float4* xp = (float4*)(g_x2 + (size_t)n * Hh) + t;
    float4 xv = *xp;
    xv.x += fmaxf((v.x - mu) * rstd * g.x + b.x, 0.f);
    xv.y += fmaxf((v.y - mu) * rstd * g.y + b.y, 0.f);
    xv.z += fmaxf((v.z - mu) * rstd * g.z + b.z, 0.f);
    xv.w += fmaxf((v.w - mu) * rstd * g.w + b.w, 0.f);
    *xp = xv;
}

// ---------------- final reduce ----------------
__global__ void final_k(const int* __restrict__ pairs,
                        const int* __restrict__ degrees,
                        const float* __restrict__ w2,
                        const float* __restrict__ b2,
                        const float* __restrict__ alpha,
                        const float* __restrict__ beta,
                        float* __restrict__ out) {
    int warp = (blockIdx.x * blockDim.x + threadIdx.x) >> 5;
    int lane = threadIdx.x & 31;
    if (warp >= Pp) return;
    const float* h1 = g_h1 + (size_t)warp * Dd;
    float s = 0.f;
#pragma unroll
    for (int j = lane; j < Dd; j += 32) s += h1[j] * w2[j];
#pragma unroll
    for (int o = 16; o; o >>= 1) s += __shfl_xor_sync(0xffffffff, s, o);
    if (lane == 0) {
        float sc = s + b2[0];
        int spi = pairs[warp], dpi = pairs[Pp + warp];
        float sd = fmaxf((float)degrees[spi], 1.f);
        float dd = fmaxf((float)degrees[dpi], 1.f);
        float ra = fmaxf(alpha[0], 0.f), rb = fmaxf(beta[0], 0.f);
        float base = sc - ra * logf(sd) - rb * logf(dd);
        out[warp] = base / (sqrtf(sd) * sqrtf(dd) + 1e-8f);
    }
}

// ---------------- launch ----------------
extern "C" void kernel_launch(void* const* d_in, const int* in_sizes, int n_in,
                              void* d_out, int out_size) {
    const int*   types     = (const int*)d_in[0];
    const int*   src0      = (const int*)d_in[1];
    const int*   dst0      = (const int*)d_in[2];
    const int*   src1      = (const int*)d_in[3];
    const int*   dst1      = (const int*)d_in[4];
    const int*   src2      = (const int*)d_in[5];
    const int*   dst2      = (const int*)d_in[6];
    const int*   pairs     = (const int*)d_in[7];
    const int*   degrees   = (const int*)d_in[8];
    const float* node_emb  = (const float*)d_in[9];
    const float* type_emb  = (const float*)d_in[10];
    const float* w_loop_in  = (const float*)d_in[11];
    const float* w_rel_in   = (const float*)d_in[12];
    const float* w_loop_res = (const float*)d_in[13];
    const float* w_rel_res  = (const float*)d_in[14];
    const float* ln_g       = (const float*)d_in[15];
    const float* ln_b       = (const float*)d_in[16];
    const float* w_loop_out = (const float*)d_in[17];
    const float* w_rel_out  = (const float*)d_in[18];
    const float* lp_w1      = (const float*)d_in[19];
    const float* lp_b1      = (const float*)d_in[20];
    const float* bn_g       = (const float*)d_in[21];
    const float* bn_b       = (const float*)d_in[22];
    const float* bn_mean    = (const float*)d_in[23];
    const float* bn_var     = (const float*)d_in[24];
    const float* lp_w2      = (const float*)d_in[25];
    const float* lp_b2      = (const float*)d_in[26];
    const float* alpha      = (const float*)d_in[27];
    const float* beta       = (const float*)d_in[28];
    float* out = (float*)d_out;

    // device-global pointers for kernel args
    float *px, *px2, *ph, *pz;
    cudaGetSymbolAddress((void**)&px,  g_x);
    cudaGetSymbolAddress((void**)&px2, g_x2);
    cudaGetSymbolAddress((void**)&ph,  g_h);
    cudaGetSymbolAddress((void**)&pz,  g_z);

    cudaFuncSetAttribute(rgcn_mma_k<512, true>,
                         cudaFuncAttributeMaxDynamicSharedMemorySize, SMEM_MMA);
    cudaFuncSetAttribute(rgcn_mma_k<512, false>,
                         cudaFuncAttributeMaxDynamicSharedMemorySize, SMEM_MMA);
    cudaFuncSetAttribute(rgcn_mma_k<256, false>,
                         cudaFuncAttributeMaxDynamicSharedMemorySize, SMEM_MMA);
    cudaFuncSetAttribute(score_mma_k,
                         cudaFuncAttributeMaxDynamicSharedMemorySize, SMEM_MMA);

    const int ENC_BLKS = (Nn * (Hh / 4) + 255) / 256;
    const int E_BLKS   = (Ee + 255) / 256;
    const int Z_BLKS   = (3 * Nn + 255) / 256;
    const int WT512    = (int)(((long)512 * KS + 255) / 256);
    const int WT256    = (int)(((long)256 * KS + 255) / 256);
    const int WTS      = (256 * 768 + 255) / 256;
    const dim3 G1(512 / NTT, (Nn + MT - 1) / MT);
    const dim3 G3(256 / NTT, (Nn + MT - 1) / MT);
    const dim3 GSc(256 / NTT, (Pp + MT - 1) / MT);
    const dim3 GAGG(Nn, 3);
    const dim3 GSCAN(SCNB, 3);

    encode_k<<<ENC_BLKS, 256>>>(types, node_emb, type_emb);

    // ---- CSR build (once per launch) ----
    csr_zero_k<<<Z_BLKS, 256>>>();
    csr_count_k<<<E_BLKS, 256>>>(dst0, dst1, dst2);
    csr_scan1_k<<<GSCAN, SCB>>>();
    csr_scan2_k<<<3, 32>>>();
    csr_scan3_k<<<GSCAN, SCB>>>();
    csr_fill_k<<<E_BLKS, 256>>>(src0, dst0, src1, dst1, src2, dst2);

    // ---- layer 1: x2 = relu(rgcn(x)) ----
    wt_build_k<<<WT512, 256>>>(w_loop_in, w_rel_in, 512);
    agg_k<<<GAGG, 128>>>(px);
    rgcn_mma_k<512, true><<<G1, 256, SMEM_MMA>>>(px, px2);

    // ---- layer 2: h = rgcn(x2); x2 += relu(LN(h)) ----
    wt_build_k<<<WT512, 256>>>(w_loop_res, w_rel_res, 512);
    agg_k<<<GAGG, 128>>>(px2);
    rgcn_mma_k<512, false><<<G1, 256, SMEM_MMA>>>(px2, ph);
    ln_relu_add_k<<<Nn, 128>>>(ln_g, ln_b);

    // ---- layer 3: z = rgcn(x2) ----
    wt_build_k<<<WT256, 256>>>(w_loop_out, w_rel_out, 256);
    agg_k<<<GAGG, 128>>>(px2);
    rgcn_mma_k<256, false><<<G3, 256, SMEM_MMA>>>(px2, pz);

    // ---- scoring ----
    wt_build_score_k<<<WTS, 256>>>(lp_w1);
    score_mma_k<<<GSc, 256, SMEM_MMA>>>(pairs, lp_b1, bn_g, bn_b, bn_mean, bn_var);
    final_k<<<(Pp * 32 + 255) / 256, 256>>>(pairs, degrees, lp_w2, lp_b2,
                                            alpha, beta, out);
}